// round 1
// baseline (speedup 1.0000x reference)
#include <cuda_runtime.h>
#include <math_constants.h>

// 9x9 max "dilation", SAME padding with -inf border, fused separable
// (horizontal 9-max then vertical 9-max) in one kernel via shared memory.
//
// Tile: 128 (x) by 32 (y) outputs per block, halo 4 each side.
//   s_in : 40 x 136 floats (loaded from global, -inf outside image)
//   s_mid: 40 x 128 floats (horizontal 9-max)
//   out  : 32 x 128 (vertical 9-max of s_mid)
//
// "Shared middle" trick: 4 adjacent outputs share the 6-element middle of
// their 9-windows -> 17 fmax / 12 loads per 4 outputs.

#define TX 128
#define TY 32
#define HALO 4
#define IN_W (TX + 2 * HALO)   // 136 (multiple of 4 -> float4 aligned rows)
#define IN_H (TY + 2 * HALO)   // 40
#define THREADS 256

__global__ __launch_bounds__(THREADS)
void dilate9_kernel(const float* __restrict__ in, float* __restrict__ out,
                    int H, int W) {
    __shared__ float s_in[IN_H][IN_W];
    __shared__ float s_mid[IN_H][TX];

    const int gx0 = blockIdx.x * TX;
    const int gy0 = blockIdx.y * TY;
    const long base = (long)blockIdx.z * H * W;
    const int tid = threadIdx.x;
    const float NEG = -CUDART_INF_F;

    // ---- Phase 1: load (IN_H x IN_W) tile into smem, -inf outside image ----
    // IN_W/4 = 34 float4 chunks per row; gx0-4 is a multiple of 4 -> aligned.
    for (int idx = tid; idx < IN_H * (IN_W / 4); idx += THREADS) {
        const int row = idx / (IN_W / 4);
        const int c4  = idx % (IN_W / 4);
        const int gy = gy0 - HALO + row;
        const int gx = gx0 - HALO + c4 * 4;
        float4 v;
        if (gy >= 0 && gy < H) {
            if (gx >= 0 && gx + 3 < W) {
                v = *(const float4*)(in + base + (long)gy * W + gx);
            } else {
                const float* rp = in + base + (long)gy * W;
                v.x = (gx + 0 >= 0 && gx + 0 < W) ? rp[gx + 0] : NEG;
                v.y = (gx + 1 >= 0 && gx + 1 < W) ? rp[gx + 1] : NEG;
                v.z = (gx + 2 >= 0 && gx + 2 < W) ? rp[gx + 2] : NEG;
                v.w = (gx + 3 >= 0 && gx + 3 < W) ? rp[gx + 3] : NEG;
            }
        } else {
            v = make_float4(NEG, NEG, NEG, NEG);
        }
        *(float4*)&s_in[row][c4 * 4] = v;
    }
    __syncthreads();

    // ---- Phase 2: horizontal 9-max. mid[r][x] = max(s_in[r][x .. x+8]) ----
    // Groups of 4 adjacent x: read 12 floats (3x float4), shared middle of 6.
    for (int gi = tid; gi < IN_H * (TX / 4); gi += THREADS) {
        const int row = gi / (TX / 4);
        const int x0  = (gi % (TX / 4)) * 4;
        const float4 a = *(const float4*)&s_in[row][x0];
        const float4 b = *(const float4*)&s_in[row][x0 + 4];
        const float4 c = *(const float4*)&s_in[row][x0 + 8];
        // shared middle: cols x0+3 .. x0+8
        const float m = fmaxf(fmaxf(fmaxf(a.w, b.x), fmaxf(b.y, b.z)),
                              fmaxf(b.w, c.x));
        float4 o;
        o.x = fmaxf(m, fmaxf(fmaxf(a.x, a.y), a.z));        // x0   : +a0,a1,a2
        o.y = fmaxf(m, fmaxf(fmaxf(a.y, a.z), c.y));        // x0+1 : +a1,a2,c1
        o.z = fmaxf(m, fmaxf(fmaxf(a.z, c.y), c.z));        // x0+2 : +a2,c1,c2
        o.w = fmaxf(m, fmaxf(fmaxf(c.y, c.z), c.w));        // x0+3 : +c1,c2,c3
        *(float4*)&s_mid[row][x0] = o;
    }
    __syncthreads();

    // ---- Phase 3: vertical 9-max + store. out[y][x] = max(mid[y..y+8][x]) --
    // Groups of 4 adjacent y per (x). Lanes take consecutive x -> conflict-free
    // LDS and coalesced STG.
    for (int gi = tid; gi < (TY / 4) * TX; gi += THREADS) {
        const int x  = gi % TX;
        const int y0 = (gi / TX) * 4;
        const float r0  = s_mid[y0 + 0][x];
        const float r1  = s_mid[y0 + 1][x];
        const float r2  = s_mid[y0 + 2][x];
        const float r3  = s_mid[y0 + 3][x];
        const float r4  = s_mid[y0 + 4][x];
        const float r5  = s_mid[y0 + 5][x];
        const float r6  = s_mid[y0 + 6][x];
        const float r7  = s_mid[y0 + 7][x];
        const float r8  = s_mid[y0 + 8][x];
        const float r9  = s_mid[y0 + 9][x];
        const float r10 = s_mid[y0 + 10][x];
        const float r11 = s_mid[y0 + 11][x];
        // shared middle: rows y0+3 .. y0+8
        const float m = fmaxf(fmaxf(fmaxf(r3, r4), fmaxf(r5, r6)),
                              fmaxf(r7, r8));
        const float o0 = fmaxf(m, fmaxf(fmaxf(r0, r1), r2));
        const float o1 = fmaxf(m, fmaxf(fmaxf(r1, r2), r9));
        const float o2 = fmaxf(m, fmaxf(fmaxf(r2, r9), r10));
        const float o3 = fmaxf(m, fmaxf(fmaxf(r9, r10), r11));

        float* op = out + base + (long)(gy0 + y0) * W + gx0 + x;
        op[0 * W] = o0;
        op[1 * W] = o1;
        op[2 * W] = o2;
        op[3 * W] = o3;
    }
}

extern "C" void kernel_launch(void* const* d_in, const int* in_sizes, int n_in,
                              void* d_out, int out_size) {
    const float* in = (const float*)d_in[0];
    float* out = (float*)d_out;
    const int H = 1024, W = 1024;
    const int N = in_sizes[0] / (H * W);   // 16
    dim3 grid(W / TX, H / TY, N);
    dilate9_kernel<<<grid, THREADS>>>(in, out, H, W);
}